// round 7
// baseline (speedup 1.0000x reference)
#include <cuda_runtime.h>
#include <cuda_bf16.h>
#include <math.h>

// Problem dims
#define Hn 512
#define Dn 128
#define Nn 64
#define Tn 512

// K3 layout: 128 persistent CTAs = 8 n-groups x 16 j-slices
#define GB_NB 128
#define K3_J  16
#define K3_NP 8          // sequences per CTA
#define K3_JC 32         // hidden-state columns per CTA
#define AP    516        // padded smem row stride (floats): conflict-free LDS.128

// ---------------- device scratch (static globals: no allocation) -------------
__device__ float g_E[(size_t)Tn * Nn * Hn];   // emit, then exp(emit - m); [t][n][h]
__device__ float g_M[Tn * Nn];                // rowmax m[t][n]
__device__ float g_Wt[Dn * Hn];               // W^T: [d][h]
__device__ float g_bias[Hn];
__device__ float g_alpha[2][(size_t)Nn * Hn]; // double-buffered scaled alpha
__device__ unsigned g_cnt = 0;
__device__ volatile unsigned g_gen = 0;

// ---------------- K0: W^T and bias ------------------------------------------
__global__ void hmm_k0(const float* __restrict__ py) {
    int h = blockIdx.x * 8 + (threadIdx.x >> 5);
    int lane = threadIdx.x & 31;
    float s = 0.f;
#pragma unroll
    for (int c = 0; c < 4; c++) {
        int d = lane + c * 32;
        float p = __ldg(py + (size_t)h * Dn + d);
        float l1 = log1pf(-p);
        g_Wt[(size_t)d * Hn + h] = logf(p) - l1;
        s += l1;
    }
#pragma unroll
    for (int o = 16; o; o >>= 1) s += __shfl_xor_sync(0xffffffffu, s, o);
    if (lane == 0) g_bias[h] = s;
}

// ---------------- K1: emission GEMM  emit[t][n][h] = seq[n,t,:]*W^T + b ------
// grid (4, 512): x = h-block of 128, y = t. CTA tile: 64 rows (n) x 128 h, K=128.
#define K1_SMEM ((64 * 132 + 128 * 128) * 4)
__global__ void __launch_bounds__(256) hmm_k1(const float* __restrict__ seq) {
    extern __shared__ float sm1[];
    float* seq_s = sm1;              // [64][132] row-major (padded)
    float* W_s   = sm1 + 64 * 132;   // [128 k][128 h]

    int tid = threadIdx.x;
    int tb = blockIdx.y;             // t
    int h0 = blockIdx.x * 128;

    // load seq tile (rows n = 0..63 at fixed t)
    for (int idx = tid; idx < 64 * 32; idx += 256) {
        int n = idx >> 5, d4 = idx & 31;
        float4 v = __ldg((const float4*)(seq + ((size_t)n * Tn + tb) * Dn + d4 * 4));
        *(float4*)&seq_s[n * 132 + d4 * 4] = v;
    }
    // load W^T block: W_s[k][h-local]
    for (int idx = tid; idx < 128 * 32; idx += 256) {
        int k = idx >> 5, h4 = idx & 31;
        float4 v = __ldg((const float4*)(g_Wt + (size_t)k * Hn + h0 + h4 * 4));
        *(float4*)&W_s[k * 128 + h4 * 4] = v;
    }
    __syncthreads();

    int tx = tid & 15;   // h:   h0 + tx*8 .. +7
    int ty = tid >> 4;   // row: ty*4 .. +3
    float acc[4][8];
#pragma unroll
    for (int u = 0; u < 4; u++)
#pragma unroll
        for (int v = 0; v < 8; v++) acc[u][v] = 0.f;

#pragma unroll 4
    for (int k = 0; k < 128; k++) {
        float aa[4];
#pragma unroll
        for (int u = 0; u < 4; u++) aa[u] = seq_s[(ty * 4 + u) * 132 + k];
        float4 b0 = *(const float4*)&W_s[k * 128 + tx * 8];
        float4 b1 = *(const float4*)&W_s[k * 128 + tx * 8 + 4];
        float bb[8] = {b0.x, b0.y, b0.z, b0.w, b1.x, b1.y, b1.z, b1.w};
#pragma unroll
        for (int u = 0; u < 4; u++)
#pragma unroll
            for (int v = 0; v < 8; v++) acc[u][v] = fmaf(aa[u], bb[v], acc[u][v]);
    }

    float4 bi0 = *(const float4*)&g_bias[h0 + tx * 8];
    float4 bi1 = *(const float4*)&g_bias[h0 + tx * 8 + 4];
    float bb[8] = {bi0.x, bi0.y, bi0.z, bi0.w, bi1.x, bi1.y, bi1.z, bi1.w};
#pragma unroll
    for (int u = 0; u < 4; u++) {
        size_t r = (size_t)tb * 64 + ty * 4 + u;
        float4 o0 = make_float4(acc[u][0] + bb[0], acc[u][1] + bb[1],
                                acc[u][2] + bb[2], acc[u][3] + bb[3]);
        float4 o1 = make_float4(acc[u][4] + bb[4], acc[u][5] + bb[5],
                                acc[u][6] + bb[6], acc[u][7] + bb[7]);
        *(float4*)&g_E[r * Hn + h0 + tx * 8]     = o0;
        *(float4*)&g_E[r * Hn + h0 + tx * 8 + 4] = o1;
    }
}

// ---------------- K2: rowmax + exp(emit - m), in place; write m --------------
__global__ void __launch_bounds__(256) hmm_k2() {
    int r = blockIdx.x * 8 + (threadIdx.x >> 5);
    int lane = threadIdx.x & 31;
    float* row = g_E + (size_t)r * Hn;
    float4 v[4];
    float m = -3.0e38f;
#pragma unroll
    for (int c = 0; c < 4; c++) {
        v[c] = *(const float4*)(row + c * 128 + lane * 4);
        m = fmaxf(m, fmaxf(fmaxf(v[c].x, v[c].y), fmaxf(v[c].z, v[c].w)));
    }
#pragma unroll
    for (int o = 16; o; o >>= 1) m = fmaxf(m, __shfl_xor_sync(0xffffffffu, m, o));
#pragma unroll
    for (int c = 0; c < 4; c++) {
        float4 e = make_float4(__expf(v[c].x - m), __expf(v[c].y - m),
                               __expf(v[c].z - m), __expf(v[c].w - m));
        *(float4*)(row + c * 128 + lane * 4) = e;
    }
    if (lane == 0) g_M[r] = m;
}

// ---------------- grid barrier (generation-based, self-resetting) ------------
__device__ __forceinline__ void gridbar() {
    __threadfence();
    __syncthreads();
    if (threadIdx.x == 0) {
        unsigned gen = g_gen;
        unsigned a = atomicAdd(&g_cnt, 1u);
        if (a == GB_NB - 1u) {
            atomicExch(&g_cnt, 0u);
            __threadfence();
            g_gen = gen + 1u;
        } else {
            while (g_gen == gen) { }
            __threadfence();
        }
    }
    __syncthreads();
}

// ---------------- K3: persistent scaled-forward recursion --------------------
#define K3_SMEM ((K3_JC * AP + K3_NP * AP + 16) * 4)
__global__ void __launch_bounds__(256, 1) hmm_k3(const float* __restrict__ px,
                                                 const int* __restrict__ lengths,
                                                 float* __restrict__ out) {
    extern __shared__ float sm3[];
    float* P_s   = sm3;                           // [K3_JC][AP]
    float* a_s   = sm3 + K3_JC * AP;              // [K3_NP][AP]
    float* S_s   = a_s + K3_NP * AP;              // [8]
    int*   len_s = (int*)(S_s + 8);               // [8]

    const int tid  = threadIdx.x;
    const int w    = tid >> 5;
    const int lane = tid & 31;
    const int cta  = blockIdx.x;
    const int jsl  = cta & (K3_J - 1);            // j-slice 0..15
    const int g    = cta >> 4;                    // n-group 0..7
    const int n0   = g * K3_NP;
    const int j0   = jsl * K3_JC;

    // P slice -> smem: P_s[jc][i] = px[i*512 + j0+jc]
    for (int idx = tid; idx < 512 * K3_JC; idx += 256) {
        int jc = idx & 31, i = idx >> 5;
        P_s[jc * AP + i] = __ldg(px + (size_t)i * Hn + j0 + jc);
    }
    if (tid < K3_NP) len_s[tid] = __ldg(lengths + n0 + tid);
    __syncthreads();

    const int nloc  = lane >> 2;
    const int jq    = lane & 3;
    const int jrow  = (w << 2) | jq;              // 0..31 local column
    const int jglob = j0 + jrow;
    const int nglob = n0 + nloc;
    const size_t arow_off = (size_t)nglob * Hn + jglob;

    // ---- t = 0 init: a0 = probs_x[0][j] * E[0][n][j];  C = m0 ----
    float accv;
    {
        float e0 = __ldcg(g_E + arow_off);        // t=0 slice
        float p0 = __ldg(px + jglob);             // probs_x row 0
        accv = p0 * e0;
        g_alpha[0][arow_off] = accv;
    }
    float Creg = 0.f;
    if (jsl == 0 && lane == 0) Creg = __ldg(g_M + n0 + w);  // m[0][n0+w]
    gridbar();

    for (int t = 1; t < Tn; t++) {
        const int rb = (t - 1) & 1;
        const int wb = t & 1;

        // stage alpha: warp w owns sequence n0+w; deterministic row sum -> S
        {
            const float* ar = g_alpha[rb] + (size_t)(n0 + w) * Hn;
            float ssum = 0.f;
#pragma unroll
            for (int c = 0; c < 4; c++) {
                int i = c * 128 + lane * 4;
                float4 v = __ldcg((const float4*)(ar + i));
                ssum += (v.x + v.y) + (v.z + v.w);
                *(float4*)&a_s[w * AP + i] = v;
            }
#pragma unroll
            for (int o = 16; o; o >>= 1) ssum += __shfl_xor_sync(0xffffffffu, ssum, o);
            if (lane == 0) {
                S_s[w] = ssum;
                if (jsl == 0 && t < len_s[w])
                    Creg += logf(ssum) + __ldg(g_M + (size_t)t * Nn + n0 + w);
            }
        }
        __syncthreads();

        // E prefetch (independent of a_s)
        float e = __ldcg(g_E + (size_t)t * Nn * Hn + arow_off);

        // dot over 512 previous states
        const float* ap = a_s + nloc * AP;
        const float* pp = P_s + jrow * AP;
        float q0 = 0.f, q1 = 0.f, q2 = 0.f, q3 = 0.f;
#pragma unroll 4
        for (int i = 0; i < 512; i += 8) {
            float4 a0 = *(const float4*)(ap + i);
            float4 p0 = *(const float4*)(pp + i);
            float4 a1 = *(const float4*)(ap + i + 4);
            float4 p1 = *(const float4*)(pp + i + 4);
            q0 = fmaf(a0.x, p0.x, q0); q1 = fmaf(a0.y, p0.y, q1);
            q2 = fmaf(a0.z, p0.z, q2); q3 = fmaf(a0.w, p0.w, q3);
            q0 = fmaf(a1.x, p1.x, q0); q1 = fmaf(a1.y, p1.y, q1);
            q2 = fmaf(a1.z, p1.z, q2); q3 = fmaf(a1.w, p1.w, q3);
        }
        float tmp = (q0 + q1) + (q2 + q3);
        float rinv = 1.0f / S_s[nloc];
        float newv = tmp * rinv * e;
        if (t < len_s[nloc]) accv = newv;          // frozen lanes copy-through
        g_alpha[wb][arow_off] = accv;
        gridbar();
    }

    // ---- output: j-slice-0 CTAs finish their 8 sequences ----
    if (jsl == 0) {
        const float* ar = g_alpha[(Tn - 1) & 1] + (size_t)(n0 + w) * Hn;
        float ssum = 0.f;
#pragma unroll
        for (int c = 0; c < 4; c++) {
            int i = c * 128 + lane * 4;
            float4 v = __ldcg((const float4*)(ar + i));
            ssum += (v.x + v.y) + (v.z + v.w);
        }
#pragma unroll
        for (int o = 16; o; o >>= 1) ssum += __shfl_xor_sync(0xffffffffu, ssum, o);
        if (lane == 0) out[n0 + w] = Creg + logf(ssum);
    }
}

// ---------------- launch ------------------------------------------------------
extern "C" void kernel_launch(void* const* d_in, const int* in_sizes, int n_in,
                              void* d_out, int out_size) {
    const float* seq = nullptr;
    const int*   len = nullptr;
    const float* px  = nullptr;
    const float* py  = nullptr;
    for (int i = 0; i < n_in; i++) {
        switch (in_sizes[i]) {
            case Nn * Tn * Dn: seq = (const float*)d_in[i]; break;  // 4194304
            case Nn:           len = (const int*)d_in[i];   break;  // 64
            case Hn * Hn:      px  = (const float*)d_in[i]; break;  // 262144
            case Hn * Dn:      py  = (const float*)d_in[i]; break;  // 65536
        }
    }

    cudaFuncSetAttribute(hmm_k1, cudaFuncAttributeMaxDynamicSharedMemorySize, K1_SMEM);
    cudaFuncSetAttribute(hmm_k3, cudaFuncAttributeMaxDynamicSharedMemorySize, K3_SMEM);

    hmm_k0<<<64, 256>>>(py);
    hmm_k1<<<dim3(4, 512), 256, K1_SMEM>>>(seq);
    hmm_k2<<<4096, 256>>>();
    hmm_k3<<<GB_NB, 256, K3_SMEM>>>(px, len, (float*)d_out);
}